// round 13
// baseline (speedup 1.0000x reference)
#include <cuda_runtime.h>
#include <cuda_bf16.h>
#include <math.h>
#include <stdint.h>

// Problem dims (fixed)
#define BATCH 8
#define N1    2048
#define N2    2048
#define DIM   1024

// ---------------------------------------------------------------------------
// Scratch arena, dual-plane (h|l) operand encoding (R12 layout, passing).
//   R1 @ 0         (64MB): Xm_h|Xm_l -> K_h|K_l -> P_l
//   R2 @ 67108864  (64MB): Xf_h|Xf_l            (dead after V proj)
//   R3 @ 134217728 (64MB): Q_h|Q_l  -> P_h
//   R4 @ 201326592 (64MB): Vt_h|Vt_l
//   R5 @ 268435456 (128MB): S (fp32)
//   R6 @ 402653184 (12MB): Wq_h,Wq_l,Wk_h,Wk_l,Wv_h,Wv_l (2MB each)
// ---------------------------------------------------------------------------
#define HALF32  ((size_t)33554432)
#define OFF_R1  ((size_t)0)
#define OFF_R2  ((size_t)67108864)
#define OFF_R3  ((size_t)134217728)
#define OFF_R4  ((size_t)201326592)
#define OFF_R5  ((size_t)268435456)
#define OFF_R6  ((size_t)402653184)
#define WPLANE  ((size_t)2097152)
#define ARENA_BYTES ((size_t)415236096)

__device__ __align__(1024) unsigned char g_arena[ARENA_BYTES];

// ---------------------------------------------------------------------------
// PTX helpers (legacy mma.sync path; tcgen05 unavailable on this harness)
// ---------------------------------------------------------------------------
__device__ __forceinline__ uint32_t smem_u32(const void* p) {
    return (uint32_t)__cvta_generic_to_shared(p);
}
__device__ __forceinline__ void cp_async16(uint32_t dst, const void* src) {
    asm volatile("cp.async.cg.shared.global [%0], [%1], 16;\n" :: "r"(dst), "l"(src));
}
__device__ __forceinline__ void cp_commit() {
    asm volatile("cp.async.commit_group;\n");
}
__device__ __forceinline__ void cp_wait1() {
    asm volatile("cp.async.wait_group 1;\n");
}
__device__ __forceinline__ void ldsm4(uint32_t& r0, uint32_t& r1, uint32_t& r2, uint32_t& r3,
                                      uint32_t addr) {
    asm volatile("ldmatrix.sync.aligned.m8n8.x4.shared.b16 {%0,%1,%2,%3}, [%4];\n"
                 : "=r"(r0), "=r"(r1), "=r"(r2), "=r"(r3) : "r"(addr));
}
__device__ __forceinline__ void mma16816(float* d, const uint32_t* a, uint32_t b0, uint32_t b1) {
    asm volatile("mma.sync.aligned.m16n8k16.row.col.f32.bf16.bf16.f32 "
                 "{%0,%1,%2,%3}, {%4,%5,%6,%7}, {%8,%9}, {%0,%1,%2,%3};\n"
                 : "+f"(d[0]), "+f"(d[1]), "+f"(d[2]), "+f"(d[3])
                 : "r"(a[0]), "r"(a[1]), "r"(a[2]), "r"(a[3]), "r"(b0), "r"(b1));
}
__device__ __forceinline__ uint32_t pkbf(__nv_bfloat16 a, __nv_bfloat16 b) {
    return (uint32_t)__bfloat16_as_ushort(a) | ((uint32_t)__bfloat16_as_ushort(b) << 16);
}

// R4-validated swizzle: logical [128 rows][32 k] bf16 (64B rows), two logical
// rows packed per 128B physical row, 16B chunks XORed -> conflict-free.
__device__ __forceinline__ uint32_t sw_off(int r, int c) {
    int pr = r >> 1;
    int pc = ((r & 1) << 2) | c;
    return (uint32_t)(pr * 128 + ((pc ^ (pr & 7)) << 4));
}

// ---------------------------------------------------------------------------
// Dual-plane NT bf16 GEMM:  C = Ah*Bh^T + Ah*Bl^T + Al*Bh^T  (fp32 accum)
// CTA tile 128x128, BK=32, 256 threads (2x4 warps, 64x32/warp), 3-stage
// cp.async ring, one sync/iter, 2 CTAs/SM.  Per warp-stage: 24 ldsm, 96 MMA.
// CTA raster swizzle (GW=8) groups 8 M-blocks per N-column for L2 locality.
// OM: 0 fp32 out; 1 dual h/l out; 2 dual h/l out transposed (Vt), staged
//     through smem for coalesced stores.
// ---------------------------------------------------------------------------
#define BM 128
#define BN 128
#define BK 32
#define STAGES 3
#define STG_BYTES 32768u          // Ah 8K | Al 8K | Bh 8K | Bl 8K
#define SMEM_DYN  (STAGES * STG_BYTES)
#define GW 8                      // raster group width (gy % 8 == 0 for all grids)

__device__ __forceinline__ void load_stage2(const __nv_bfloat16* Ah, const __nv_bfloat16* Al,
                                            const __nv_bfloat16* Bh, const __nv_bfloat16* Bl,
                                            int K, int mBase, int nBase,
                                            uint32_t sbase, int s, int k0, int tid)
{
    const uint32_t st = sbase + (uint32_t)s * STG_BYTES;
#pragma unroll
    for (int p = 0; p < 2; p++) {
        int id = tid + p * 256;       // 0..511
        int r  = id >> 2;             // 0..127
        int c  = id & 3;              // 0..3
        uint32_t u = sw_off(r, c);
        const size_t ao = (size_t)(mBase + r) * K + k0 + c * 8;
        const size_t bo = (size_t)(nBase + r) * K + k0 + c * 8;
        cp_async16(st + u,           Ah + ao);
        cp_async16(st + 8192u + u,   Al + ao);
        cp_async16(st + 16384u + u,  Bh + bo);
        cp_async16(st + 24576u + u,  Bl + bo);
    }
    cp_commit();
}

__device__ __forceinline__ void fetch_a(uint32_t base, int wm, int lane, int ks,
                                        uint32_t a[4][4])
{
    const int lrow = lane & 15;
    const int lkc  = lane >> 4;
#pragma unroll
    for (int mi = 0; mi < 4; mi++) {
        int r = wm * 64 + mi * 16 + lrow;
        ldsm4(a[mi][0], a[mi][1], a[mi][2], a[mi][3], base + sw_off(r, ks * 2 + lkc));
    }
}
__device__ __forceinline__ void fetch_b(uint32_t base, int wn, int lane, int ks,
                                        uint32_t b[2][4])
{
    const int lrow = lane & 15;
    const int lkc  = lane >> 4;
#pragma unroll
    for (int bi = 0; bi < 2; bi++) {
        int r = wn * 32 + bi * 16 + lrow;
        ldsm4(b[bi][0], b[bi][1], b[bi][2], b[bi][3], base + sw_off(r, ks * 2 + lkc));
    }
}
__device__ __forceinline__ void mma_frags(const uint32_t a[4][4], const uint32_t b[2][4],
                                          float acc[4][4][4])
{
#pragma unroll
    for (int mi = 0; mi < 4; mi++)
#pragma unroll
        for (int ni = 0; ni < 4; ni++)
            mma16816(acc[mi][ni], a[mi], b[ni >> 1][ni & 1], b[ni >> 1][2 + (ni & 1)]);
}

template<int OM, bool HAS_BIAS>
__global__ void __launch_bounds__(256, 2)
gemm2(const __nv_bfloat16* __restrict__ Ah, const __nv_bfloat16* __restrict__ Al,
      const __nv_bfloat16* __restrict__ Bh, const __nv_bfloat16* __restrict__ Bl,
      const float* __restrict__ bias, float* __restrict__ Cf,
      __nv_bfloat16* __restrict__ Ch, __nv_bfloat16* __restrict__ Cl,
      int K, size_t strA, size_t strB, size_t strC, int ldc)
{
    extern __shared__ __align__(1024) unsigned char dsm[];
    const uint32_t sbase = smem_u32(dsm);

    Ah += (size_t)blockIdx.z * strA;
    Al += (size_t)blockIdx.z * strA;
    Bh += (size_t)blockIdx.z * strB;
    Bl += (size_t)blockIdx.z * strB;

    // CTA raster swizzle: 8 M-blocks share one N-column concurrently.
    int bxs, bys;
    {
        const int gx = gridDim.x;
        int lin  = blockIdx.y * gx + blockIdx.x;
        int span = gx * GW;
        int grpI = lin / span;
        int rem  = lin - grpI * span;
        bxs = rem / GW;
        bys = grpI * GW + (rem - (rem / GW) * GW);
    }

    const int tid  = threadIdx.x;
    const int wid  = tid >> 5, lane = tid & 31;
    const int wm   = wid >> 2, wn = wid & 3;        // 2 x 4 warp grid, 64x32 tiles
    const int mBase = bys * BM;
    const int nBase = bxs * BN;

    float acc[4][4][4];
#pragma unroll
    for (int i = 0; i < 4; i++)
#pragma unroll
        for (int j = 0; j < 4; j++)
#pragma unroll
            for (int r = 0; r < 4; r++) acc[i][j][r] = 0.f;

    const int KT = K / BK;    // 32 (proj/scores) or 64 (PV)

    load_stage2(Ah, Al, Bh, Bl, K, mBase, nBase, sbase, 0, 0,  tid);
    load_stage2(Ah, Al, Bh, Bl, K, mBase, nBase, sbase, 1, BK, tid);

    for (int kt = 0; kt < KT; kt++) {
        const int s = kt % STAGES;
        const uint32_t st = sbase + (uint32_t)s * STG_BYTES;
        cp_wait1();            // oldest outstanding group (tile kt) complete
        __syncthreads();       // tile kt visible; stage (kt+2)%3 fully consumed
        if (kt + 2 < KT)
            load_stage2(Ah, Al, Bh, Bl, K, mBase, nBase, sbase,
                        (kt + 2) % STAGES, (kt + 2) * BK, tid);
        else
            cp_commit();       // empty group keeps wait_group FIFO arithmetic exact

#pragma unroll
        for (int ks = 0; ks < 2; ks++) {
            uint32_t a_h[4][4], b_h[2][4];
            fetch_a(st,           wm, lane, ks, a_h);
            fetch_b(st + 16384u,  wn, lane, ks, b_h);
            mma_frags(a_h, b_h, acc);            // Ah * Bh
            {
                uint32_t a_l[4][4];
                fetch_a(st + 8192u, wm, lane, ks, a_l);
                mma_frags(a_l, b_h, acc);        // Al * Bh
            }
            {
                uint32_t b_l[2][4];
                fetch_b(st + 24576u, wn, lane, ks, b_l);
                mma_frags(a_h, b_l, acc);        // Ah * Bl
            }
        }
    }

    // ---- epilogue ----
    const int grp = lane >> 2, qid = lane & 3;

    if (OM == 0) {
        float* C = Cf + (size_t)blockIdx.z * strC;
#pragma unroll
        for (int mi = 0; mi < 4; mi++)
#pragma unroll
            for (int ni = 0; ni < 4; ni++) {
                int m0 = mBase + wm * 64 + mi * 16 + grp;
                int n0 = nBase + wn * 32 + ni * 8 + qid * 2;
                *(float2*)(C + (size_t)m0 * ldc + n0) =
                    make_float2(acc[mi][ni][0], acc[mi][ni][1]);
                *(float2*)(C + (size_t)(m0 + 8) * ldc + n0) =
                    make_float2(acc[mi][ni][2], acc[mi][ni][3]);
            }
    } else if (OM == 1) {      // dual h/l planes, row-major ldc
#pragma unroll
        for (int mi = 0; mi < 4; mi++)
#pragma unroll
            for (int ni = 0; ni < 4; ni++) {
                int m0 = mBase + wm * 64 + mi * 16 + grp;
                int n0 = nBase + wn * 32 + ni * 8 + qid * 2;
                float bv0 = HAS_BIAS ? bias[n0]     : 0.f;
                float bv1 = HAS_BIAS ? bias[n0 + 1] : 0.f;
#pragma unroll
                for (int rr = 0; rr < 2; rr++) {
                    int m = m0 + rr * 8;
                    float c0 = acc[mi][ni][rr * 2 + 0] + bv0;
                    float c1 = acc[mi][ni][rr * 2 + 1] + bv1;
                    __nv_bfloat16 h0 = __float2bfloat16(c0);
                    __nv_bfloat16 l0 = __float2bfloat16(c0 - __bfloat162float(h0));
                    __nv_bfloat16 h1 = __float2bfloat16(c1);
                    __nv_bfloat16 l1 = __float2bfloat16(c1 - __bfloat162float(h1));
                    *(uint32_t*)(Ch + (size_t)m * ldc + n0) = pkbf(h0, h1);
                    *(uint32_t*)(Cl + (size_t)m * ldc + n0) = pkbf(l0, l1);
                }
            }
    } else {                   // OM == 2 : Vt — stage through smem, coalesced stores
        __syncthreads();       // all warps done reading pipeline smem
        // per-warp smem region: h tile [32 n][72 mm] bf16 (pad 8) + l tile
        __nv_bfloat16* sh = (__nv_bfloat16*)(dsm + wid * 9216);
        __nv_bfloat16* sl = (__nv_bfloat16*)(dsm + wid * 9216 + 4608);
#pragma unroll
        for (int mi = 0; mi < 4; mi++)
#pragma unroll
            for (int ni = 0; ni < 4; ni++) {
#pragma unroll
                for (int rr = 0; rr < 2; rr++) {
#pragma unroll
                    for (int cc = 0; cc < 2; cc++) {
                        int mloc = mi * 16 + grp + rr * 8;       // 0..63
                        int nloc = ni * 8 + qid * 2 + cc;        // 0..31
                        float c = acc[mi][ni][rr * 2 + cc]
                                + (HAS_BIAS ? bias[nBase + wn * 32 + nloc] : 0.f);
                        __nv_bfloat16 h = __float2bfloat16(c);
                        __nv_bfloat16 l = __float2bfloat16(c - __bfloat162float(h));
                        sh[nloc * 72 + mloc] = h;
                        sl[nloc * 72 + mloc] = l;
                    }
                }
            }
        __syncwarp();
        // coalesced writes: 8 lanes cover one 64-elem (128B) row; 4 rows/pass
        const int m0  = mBase + wm * 64;
        const int b   = m0 >> 11;
        const int mm0 = m0 & 2047;
        const int n0g = nBase + wn * 32;
        const int ls  = lane >> 3;           // 0..3 row-in-pass
        const int chv = (lane & 7) * 8;      // 0..56 mm chunk (8 bf16 = 16B)
#pragma unroll
        for (int p = 0; p < 8; p++) {
            int nl = p * 4 + ls;
            uint4 vh = *(uint4*)(sh + nl * 72 + chv);
            uint4 vl = *(uint4*)(sl + nl * 72 + chv);
            size_t off = (size_t)b * ((size_t)DIM * N2) + (size_t)(n0g + nl) * N2 + mm0 + chv;
            *(uint4*)(Ch + off) = vh;
            *(uint4*)(Cl + off) = vl;
        }
    }
}

// ---------------------------------------------------------------------------
// fp32 -> dual bf16 planes (h, l).  2 independent float4 per thread.
// ---------------------------------------------------------------------------
__device__ __forceinline__ void split_one2(const float* __restrict__ x,
                                           __nv_bfloat16* __restrict__ yh,
                                           __nv_bfloat16* __restrict__ yl, int i)
{
    float4 v = ((const float4*)x)[i];
    float f[4] = {v.x, v.y, v.z, v.w};
    __nv_bfloat16 h[4], l[4];
#pragma unroll
    for (int j = 0; j < 4; j++) {
        h[j] = __float2bfloat16(f[j]);
        l[j] = __float2bfloat16(f[j] - __bfloat162float(h[j]));
    }
    *(uint2*)(yh + (size_t)4 * i) = make_uint2(pkbf(h[0], h[1]), pkbf(h[2], h[3]));
    *(uint2*)(yl + (size_t)4 * i) = make_uint2(pkbf(l[0], l[1]), pkbf(l[2], l[3]));
}

__global__ void __launch_bounds__(256)
split2_kernel(const float* __restrict__ x, __nv_bfloat16* __restrict__ yh,
              __nv_bfloat16* __restrict__ yl, int n4)
{
    int i  = blockIdx.x * 256 + threadIdx.x;
    int st = gridDim.x * 256;
    if (i < n4)      split_one2(x, yh, yl, i);
    if (i + st < n4) split_one2(x, yh, yl, i + st);
}

// Batched weight split: 3 weight matrices in one launch.
__global__ void __launch_bounds__(256)
split2w_kernel(const float* __restrict__ w0, const float* __restrict__ w1,
               const float* __restrict__ w2, __nv_bfloat16* __restrict__ o0h,
               __nv_bfloat16* __restrict__ o0l, __nv_bfloat16* __restrict__ o1h,
               __nv_bfloat16* __restrict__ o1l, __nv_bfloat16* __restrict__ o2h,
               __nv_bfloat16* __restrict__ o2l, int n4)
{
    int i = blockIdx.x * 256 + threadIdx.x;
    if (i >= 3 * n4) return;
    int which = i / n4;
    int j = i - which * n4;
    const float* src = (which == 0) ? w0 : (which == 1) ? w1 : w2;
    __nv_bfloat16* yh = (which == 0) ? o0h : (which == 1) ? o1h : o2h;
    __nv_bfloat16* yl = (which == 0) ? o0l : (which == 1) ? o1l : o2l;
    split_one2(src, yh, yl, j);
}

// ---------------------------------------------------------------------------
// Softmax over 2048 fp32 logits/row -> dual bf16 planes P_h, P_l.
// ---------------------------------------------------------------------------
__global__ void __launch_bounds__(256)
softmax_split(const float* __restrict__ S, __nv_bfloat16* __restrict__ Ph,
              __nv_bfloat16* __restrict__ Pl)
{
    const float* src = S + (size_t)blockIdx.x * N2;
    __nv_bfloat16* dsth = Ph + (size_t)blockIdx.x * N2;
    __nv_bfloat16* dstl = Pl + (size_t)blockIdx.x * N2;
    const int tid = threadIdx.x;
    __shared__ float red[8];

    float4 v0 = ((const float4*)src)[tid];
    float4 v1 = ((const float4*)src)[tid + 256];

    float m = fmaxf(fmaxf(fmaxf(v0.x, v0.y), fmaxf(v0.z, v0.w)),
                    fmaxf(fmaxf(v1.x, v1.y), fmaxf(v1.z, v1.w)));
#pragma unroll
    for (int o = 16; o > 0; o >>= 1) m = fmaxf(m, __shfl_xor_sync(~0u, m, o));
    if ((tid & 31) == 0) red[tid >> 5] = m;
    __syncthreads();
    if (tid < 32) {
        float t = (tid < 8) ? red[tid] : -INFINITY;
#pragma unroll
        for (int o = 4; o > 0; o >>= 1) t = fmaxf(t, __shfl_xor_sync(~0u, t, o));
        if (tid == 0) red[0] = t;
    }
    __syncthreads();
    const float rowMax = red[0];
    __syncthreads();

    v0.x = expf(v0.x - rowMax); v0.y = expf(v0.y - rowMax);
    v0.z = expf(v0.z - rowMax); v0.w = expf(v0.w - rowMax);
    v1.x = expf(v1.x - rowMax); v1.y = expf(v1.y - rowMax);
    v1.z = expf(v1.z - rowMax); v1.w = expf(v1.w - rowMax);

    float s = v0.x + v0.y + v0.z + v0.w + v1.x + v1.y + v1.z + v1.w;
#pragma unroll
    for (int o = 16; o > 0; o >>= 1) s += __shfl_xor_sync(~0u, s, o);
    if ((tid & 31) == 0) red[tid >> 5] = s;
    __syncthreads();
    if (tid < 32) {
        float t = (tid < 8) ? red[tid] : 0.f;
#pragma unroll
        for (int o = 4; o > 0; o >>= 1) t += __shfl_xor_sync(~0u, t, o);
        if (tid == 0) red[0] = t;
    }
    __syncthreads();
    const float inv = 1.0f / red[0];

#pragma unroll
    for (int g = 0; g < 2; g++) {
        float4 v = g ? v1 : v0;
        int idx = g ? (tid + 256) : tid;
        float f[4] = {v.x * inv, v.y * inv, v.z * inv, v.w * inv};
        __nv_bfloat16 h[4], l[4];
#pragma unroll
        for (int j = 0; j < 4; j++) {
            h[j] = __float2bfloat16(f[j]);
            l[j] = __float2bfloat16(f[j] - __bfloat162float(h[j]));
        }
        *(uint2*)(dsth + (size_t)4 * idx) = make_uint2(pkbf(h[0], h[1]), pkbf(h[2], h[3]));
        *(uint2*)(dstl + (size_t)4 * idx) = make_uint2(pkbf(l[0], l[1]), pkbf(l[2], l[3]));
    }
}

// ---------------------------------------------------------------------------
// Launch (R12 buffer plan, verified disjoint per step)
// ---------------------------------------------------------------------------
extern "C" void kernel_launch(void* const* d_in, const int* in_sizes, int n_in,
                              void* d_out, int out_size)
{
    const float* mainf = (const float*)d_in[0];
    const float* feat  = (const float*)d_in[1];
    const float* Wq    = (const float*)d_in[2];
    const float* bq    = (const float*)d_in[3];
    const float* Wk    = (const float*)d_in[4];
    const float* bk    = (const float*)d_in[5];
    const float* Wv    = (const float*)d_in[6];
    const float* bv    = (const float*)d_in[7];
    float* out = (float*)d_out;

    unsigned char* arena;
    cudaGetSymbolAddress((void**)&arena, g_arena);

    __nv_bfloat16* Xm_h = (__nv_bfloat16*)(arena + OFF_R1);
    __nv_bfloat16* Xm_l = (__nv_bfloat16*)(arena + OFF_R1 + HALF32);
    __nv_bfloat16* Xf_h = (__nv_bfloat16*)(arena + OFF_R2);
    __nv_bfloat16* Xf_l = (__nv_bfloat16*)(arena + OFF_R2 + HALF32);
    __nv_bfloat16* Q_h  = (__nv_bfloat16*)(arena + OFF_R3);
    __nv_bfloat16* Q_l  = (__nv_bfloat16*)(arena + OFF_R3 + HALF32);
    __nv_bfloat16* K_h  = (__nv_bfloat16*)(arena + OFF_R1);
    __nv_bfloat16* K_l  = (__nv_bfloat16*)(arena + OFF_R1 + HALF32);
    __nv_bfloat16* Vt_h = (__nv_bfloat16*)(arena + OFF_R4);
    __nv_bfloat16* Vt_l = (__nv_bfloat16*)(arena + OFF_R4 + HALF32);
    float*         S    = (float*)(arena + OFF_R5);
    __nv_bfloat16* P_h  = (__nv_bfloat16*)(arena + OFF_R3);
    __nv_bfloat16* P_l  = (__nv_bfloat16*)(arena + OFF_R1);
    __nv_bfloat16* Wq_h = (__nv_bfloat16*)(arena + OFF_R6);
    __nv_bfloat16* Wq_l = (__nv_bfloat16*)(arena + OFF_R6 + WPLANE);
    __nv_bfloat16* Wk_h = (__nv_bfloat16*)(arena + OFF_R6 + 2 * WPLANE);
    __nv_bfloat16* Wk_l = (__nv_bfloat16*)(arena + OFF_R6 + 3 * WPLANE);
    __nv_bfloat16* Wv_h = (__nv_bfloat16*)(arena + OFF_R6 + 4 * WPLANE);
    __nv_bfloat16* Wv_l = (__nv_bfloat16*)(arena + OFF_R6 + 5 * WPLANE);

    cudaFuncSetAttribute(gemm2<0, false>, cudaFuncAttributeMaxDynamicSharedMemorySize, SMEM_DYN);
    cudaFuncSetAttribute(gemm2<1, true>,  cudaFuncAttributeMaxDynamicSharedMemorySize, SMEM_DYN);
    cudaFuncSetAttribute(gemm2<2, true>,  cudaFuncAttributeMaxDynamicSharedMemorySize, SMEM_DYN);

    const int MX = BATCH * N1;   // 16384

    // 1) split-encode inputs (2 launches) and all weights (1 launch)
    {
        int n4i = MX * DIM / 4;       // 4,194,304
        int n4w = DIM * DIM / 4;      // 262,144
        split2_kernel<<<(n4i / 2 + 255) / 256, 256>>>(mainf, Xm_h, Xm_l, n4i);
        split2_kernel<<<(n4i / 2 + 255) / 256, 256>>>(feat,  Xf_h, Xf_l, n4i);
        split2w_kernel<<<(3 * n4w + 255) / 256, 256>>>(Wq, Wk, Wv,
                                                       Wq_h, Wq_l, Wk_h, Wk_l,
                                                       Wv_h, Wv_l, n4w);
    }

    // 2-4) projections: M=16384, N=1024, K=1024  (gy=128, %8==0)
    {
        dim3 g(DIM / BN, MX / BM, 1);
        gemm2<1, true><<<g, 256, SMEM_DYN>>>(Xm_h, Xm_l, Wq_h, Wq_l, bq,
                                             nullptr, Q_h, Q_l, DIM, 0, 0, 0, DIM);
        gemm2<1, true><<<g, 256, SMEM_DYN>>>(Xf_h, Xf_l, Wk_h, Wk_l, bk,
                                             nullptr, K_h, K_l, DIM, 0, 0, 0, DIM);
        gemm2<2, true><<<g, 256, SMEM_DYN>>>(Xf_h, Xf_l, Wv_h, Wv_l, bv,
                                             nullptr, Vt_h, Vt_l, DIM, 0, 0, 0, 0);
    }

    // 5) scores: per-batch M=2048, N=2048, K=1024 -> S fp32  (gy=16, %8==0)
    {
        dim3 g(N2 / BN, N1 / BM, BATCH);
        gemm2<0, false><<<g, 256, SMEM_DYN>>>(Q_h, Q_l, K_h, K_l, nullptr,
                                              S, nullptr, nullptr, DIM,
                                              (size_t)N1 * DIM, (size_t)N2 * DIM,
                                              (size_t)N1 * N2, N2);
    }

    // 6) softmax -> P_h, P_l
    softmax_split<<<BATCH * N1, 256>>>(S, P_h, P_l);

    // 7) out = P @ V : per-batch M=2048, N=1024, K=2048  (gy=16, %8==0)
    {
        dim3 g(DIM / BN, N1 / BM, BATCH);
        gemm2<0, false><<<g, 256, SMEM_DYN>>>(P_h, P_l, Vt_h, Vt_l, nullptr,
                                              out, nullptr, nullptr, N2,
                                              (size_t)N1 * N2, (size_t)DIM * N2,
                                              (size_t)N1 * DIM, DIM);
    }
}

// round 14
// speedup vs baseline: 1.0221x; 1.0221x over previous
#include <cuda_runtime.h>
#include <cuda_bf16.h>
#include <math.h>
#include <stdint.h>

// Problem dims (fixed)
#define BATCH 8
#define N1    2048
#define N2    2048
#define DIM   1024

// ---------------------------------------------------------------------------
// Scratch arena, dual-plane (h|l) operand encoding (R12 layout, passing).
//   R1 @ 0         (64MB): Xm_h|Xm_l -> K_h|K_l -> P_l
//   R2 @ 67108864  (64MB): Xf_h|Xf_l            (dead after V proj)
//   R3 @ 134217728 (64MB): Q_h|Q_l  -> P_h
//   R4 @ 201326592 (64MB): Vt_h|Vt_l
//   R5 @ 268435456 (128MB): S (fp32)
//   R6 @ 402653184 (12MB): Wq_h,Wq_l,Wk_h,Wk_l,Wv_h,Wv_l (2MB each)
// ---------------------------------------------------------------------------
#define HALF32  ((size_t)33554432)
#define OFF_R1  ((size_t)0)
#define OFF_R2  ((size_t)67108864)
#define OFF_R3  ((size_t)134217728)
#define OFF_R4  ((size_t)201326592)
#define OFF_R5  ((size_t)268435456)
#define OFF_R6  ((size_t)402653184)
#define WPLANE  ((size_t)2097152)
#define ARENA_BYTES ((size_t)415236096)

__device__ __align__(1024) unsigned char g_arena[ARENA_BYTES];

// ---------------------------------------------------------------------------
// PTX helpers (legacy mma.sync path; tcgen05 unavailable on this harness)
// ---------------------------------------------------------------------------
__device__ __forceinline__ uint32_t smem_u32(const void* p) {
    return (uint32_t)__cvta_generic_to_shared(p);
}
__device__ __forceinline__ void cp_async16(uint32_t dst, const void* src) {
    asm volatile("cp.async.cg.shared.global [%0], [%1], 16;\n" :: "r"(dst), "l"(src));
}
__device__ __forceinline__ void cp_commit() {
    asm volatile("cp.async.commit_group;\n");
}
__device__ __forceinline__ void cp_wait1() {
    asm volatile("cp.async.wait_group 1;\n");
}
__device__ __forceinline__ void ldsm4(uint32_t& r0, uint32_t& r1, uint32_t& r2, uint32_t& r3,
                                      uint32_t addr) {
    asm volatile("ldmatrix.sync.aligned.m8n8.x4.shared.b16 {%0,%1,%2,%3}, [%4];\n"
                 : "=r"(r0), "=r"(r1), "=r"(r2), "=r"(r3) : "r"(addr));
}
__device__ __forceinline__ void mma16816(float* d, const uint32_t* a, uint32_t b0, uint32_t b1) {
    asm volatile("mma.sync.aligned.m16n8k16.row.col.f32.bf16.bf16.f32 "
                 "{%0,%1,%2,%3}, {%4,%5,%6,%7}, {%8,%9}, {%0,%1,%2,%3};\n"
                 : "+f"(d[0]), "+f"(d[1]), "+f"(d[2]), "+f"(d[3])
                 : "r"(a[0]), "r"(a[1]), "r"(a[2]), "r"(a[3]), "r"(b0), "r"(b1));
}
__device__ __forceinline__ uint32_t pkbf(__nv_bfloat16 a, __nv_bfloat16 b) {
    return (uint32_t)__bfloat16_as_ushort(a) | ((uint32_t)__bfloat16_as_ushort(b) << 16);
}

// R4-validated swizzle: logical [128 rows][32 k] bf16 (64B rows), two logical
// rows packed per 128B physical row, 16B chunks XORed -> conflict-free.
__device__ __forceinline__ uint32_t sw_off(int r, int c) {
    int pr = r >> 1;
    int pc = ((r & 1) << 2) | c;
    return (uint32_t)(pr * 128 + ((pc ^ (pr & 7)) << 4));
}

// ---------------------------------------------------------------------------
// Dual-plane NT bf16 GEMM:  C = Ah*Bh^T + Ah*Bl^T + Al*Bh^T  (fp32 accum)
// CTA tile 128x128, BK=32, 256 threads (2x4 warps, 64x32/warp), 3-stage
// cp.async ring, one sync/iter, 2 CTAs/SM.  Per warp-stage: 24 ldsm, 96 MMA,
// with ALL 12 ldsm of a ks-slice issued before its 48 MMAs (one latency
// exposure instead of three; R13 profile showed tensor=56%, issue=35%).
// OM: 0 fp32 out; 1 dual h/l out; 2 dual h/l out transposed per-batch (Vt).
// ---------------------------------------------------------------------------
#define BM 128
#define BN 128
#define BK 32
#define STAGES 3
#define STG_BYTES 32768u          // Ah 8K | Al 8K | Bh 8K | Bl 8K
#define SMEM_DYN  (STAGES * STG_BYTES)

__device__ __forceinline__ void load_stage2(const __nv_bfloat16* Ah, const __nv_bfloat16* Al,
                                            const __nv_bfloat16* Bh, const __nv_bfloat16* Bl,
                                            int K, int mBase, int nBase,
                                            uint32_t sbase, int s, int k0, int tid)
{
    const uint32_t st = sbase + (uint32_t)s * STG_BYTES;
#pragma unroll
    for (int p = 0; p < 2; p++) {
        int id = tid + p * 256;       // 0..511
        int r  = id >> 2;             // 0..127
        int c  = id & 3;              // 0..3
        uint32_t u = sw_off(r, c);
        const size_t ao = (size_t)(mBase + r) * K + k0 + c * 8;
        const size_t bo = (size_t)(nBase + r) * K + k0 + c * 8;
        cp_async16(st + u,           Ah + ao);
        cp_async16(st + 8192u + u,   Al + ao);
        cp_async16(st + 16384u + u,  Bh + bo);
        cp_async16(st + 24576u + u,  Bl + bo);
    }
    cp_commit();
}

__device__ __forceinline__ void fetch_a(uint32_t base, int wm, int lane, int ks,
                                        uint32_t a[4][4])
{
    const int lrow = lane & 15;
    const int lkc  = lane >> 4;
#pragma unroll
    for (int mi = 0; mi < 4; mi++) {
        int r = wm * 64 + mi * 16 + lrow;
        ldsm4(a[mi][0], a[mi][1], a[mi][2], a[mi][3], base + sw_off(r, ks * 2 + lkc));
    }
}
__device__ __forceinline__ void fetch_b(uint32_t base, int wn, int lane, int ks,
                                        uint32_t b[2][4])
{
    const int lrow = lane & 15;
    const int lkc  = lane >> 4;
#pragma unroll
    for (int bi = 0; bi < 2; bi++) {
        int r = wn * 32 + bi * 16 + lrow;
        ldsm4(b[bi][0], b[bi][1], b[bi][2], b[bi][3], base + sw_off(r, ks * 2 + lkc));
    }
}
__device__ __forceinline__ void mma_frags(const uint32_t a[4][4], const uint32_t b[2][4],
                                          float acc[4][4][4])
{
#pragma unroll
    for (int mi = 0; mi < 4; mi++)
#pragma unroll
        for (int ni = 0; ni < 4; ni++)
            mma16816(acc[mi][ni], a[mi], b[ni >> 1][ni & 1], b[ni >> 1][2 + (ni & 1)]);
}

template<int OM, bool HAS_BIAS>
__global__ void __launch_bounds__(256, 2)
gemm2(const __nv_bfloat16* __restrict__ Ah, const __nv_bfloat16* __restrict__ Al,
      const __nv_bfloat16* __restrict__ Bh, const __nv_bfloat16* __restrict__ Bl,
      const float* __restrict__ bias, float* __restrict__ Cf,
      __nv_bfloat16* __restrict__ Ch, __nv_bfloat16* __restrict__ Cl,
      int K, size_t strA, size_t strB, size_t strC, int ldc)
{
    extern __shared__ __align__(1024) unsigned char dsm[];
    const uint32_t sbase = smem_u32(dsm);

    Ah += (size_t)blockIdx.z * strA;
    Al += (size_t)blockIdx.z * strA;
    Bh += (size_t)blockIdx.z * strB;
    Bl += (size_t)blockIdx.z * strB;

    const int tid  = threadIdx.x;
    const int wid  = tid >> 5, lane = tid & 31;
    const int wm   = wid >> 2, wn = wid & 3;        // 2 x 4 warp grid, 64x32 tiles
    const int mBase = blockIdx.y * BM;
    const int nBase = blockIdx.x * BN;

    float acc[4][4][4];
#pragma unroll
    for (int i = 0; i < 4; i++)
#pragma unroll
        for (int j = 0; j < 4; j++)
#pragma unroll
            for (int r = 0; r < 4; r++) acc[i][j][r] = 0.f;

    const int KT = K / BK;    // 32 (proj/scores) or 64 (PV)

    load_stage2(Ah, Al, Bh, Bl, K, mBase, nBase, sbase, 0, 0,  tid);
    load_stage2(Ah, Al, Bh, Bl, K, mBase, nBase, sbase, 1, BK, tid);

    for (int kt = 0; kt < KT; kt++) {
        const int s = kt % STAGES;
        const uint32_t st = sbase + (uint32_t)s * STG_BYTES;
        cp_wait1();            // oldest outstanding group (tile kt) complete
        __syncthreads();       // tile kt visible; stage (kt+2)%3 fully consumed
        if (kt + 2 < KT)
            load_stage2(Ah, Al, Bh, Bl, K, mBase, nBase, sbase,
                        (kt + 2) % STAGES, (kt + 2) * BK, tid);
        else
            cp_commit();       // empty group keeps wait_group FIFO arithmetic exact

#pragma unroll
        for (int ks = 0; ks < 2; ks++) {
            // all 12 ldsm first (one latency exposure), then 48 MMAs
            uint32_t a_h[4][4], a_l[4][4], b_h[2][4], b_l[2][4];
            fetch_a(st,           wm, lane, ks, a_h);
            fetch_b(st + 16384u,  wn, lane, ks, b_h);
            fetch_a(st + 8192u,   wm, lane, ks, a_l);
            fetch_b(st + 24576u,  wn, lane, ks, b_l);
            mma_frags(a_h, b_h, acc);            // Ah * Bh
            mma_frags(a_l, b_h, acc);            // Al * Bh
            mma_frags(a_h, b_l, acc);            // Ah * Bl
        }
    }

    // ---- epilogue ----
    const int grp = lane >> 2, qid = lane & 3;

    if (OM == 0) {
        float* C = Cf + (size_t)blockIdx.z * strC;
#pragma unroll
        for (int mi = 0; mi < 4; mi++)
#pragma unroll
            for (int ni = 0; ni < 4; ni++) {
                int m0 = mBase + wm * 64 + mi * 16 + grp;
                int n0 = nBase + wn * 32 + ni * 8 + qid * 2;
                *(float2*)(C + (size_t)m0 * ldc + n0) =
                    make_float2(acc[mi][ni][0], acc[mi][ni][1]);
                *(float2*)(C + (size_t)(m0 + 8) * ldc + n0) =
                    make_float2(acc[mi][ni][2], acc[mi][ni][3]);
            }
    } else if (OM == 1) {      // dual h/l planes, row-major ldc
#pragma unroll
        for (int mi = 0; mi < 4; mi++)
#pragma unroll
            for (int ni = 0; ni < 4; ni++) {
                int m0 = mBase + wm * 64 + mi * 16 + grp;
                int n0 = nBase + wn * 32 + ni * 8 + qid * 2;
                float bv0 = HAS_BIAS ? bias[n0]     : 0.f;
                float bv1 = HAS_BIAS ? bias[n0 + 1] : 0.f;
#pragma unroll
                for (int rr = 0; rr < 2; rr++) {
                    int m = m0 + rr * 8;
                    float c0 = acc[mi][ni][rr * 2 + 0] + bv0;
                    float c1 = acc[mi][ni][rr * 2 + 1] + bv1;
                    __nv_bfloat16 h0 = __float2bfloat16(c0);
                    __nv_bfloat16 l0 = __float2bfloat16(c0 - __bfloat162float(h0));
                    __nv_bfloat16 h1 = __float2bfloat16(c1);
                    __nv_bfloat16 l1 = __float2bfloat16(c1 - __bfloat162float(h1));
                    *(uint32_t*)(Ch + (size_t)m * ldc + n0) = pkbf(h0, h1);
                    *(uint32_t*)(Cl + (size_t)m * ldc + n0) = pkbf(l0, l1);
                }
            }
    } else {                   // OM == 2 : Vt scatter C[m][n] -> Vt[b][n][m%N2]
#pragma unroll
        for (int mi = 0; mi < 4; mi++)
#pragma unroll
            for (int ni = 0; ni < 4; ni++) {
                int m0 = mBase + wm * 64 + mi * 16 + grp;
                int n0 = nBase + wn * 32 + ni * 8 + qid * 2;
#pragma unroll
                for (int rr = 0; rr < 2; rr++) {
                    int m  = m0 + rr * 8;
                    int b  = m >> 11;
                    int mm = m & 2047;
#pragma unroll
                    for (int cc = 0; cc < 2; cc++) {
                        int n   = n0 + cc;
                        float c = acc[mi][ni][rr * 2 + cc] + (HAS_BIAS ? bias[n] : 0.f);
                        __nv_bfloat16 h = __float2bfloat16(c);
                        __nv_bfloat16 l = __float2bfloat16(c - __bfloat162float(h));
                        size_t off = (size_t)b * ((size_t)DIM * N2) + (size_t)n * N2 + mm;
                        Ch[off] = h;
                        Cl[off] = l;
                    }
                }
            }
    }
}

// ---------------------------------------------------------------------------
// fp32 -> dual bf16 planes (h, l).  2 independent float4 per thread.
// ---------------------------------------------------------------------------
__device__ __forceinline__ void split_one2(const float* __restrict__ x,
                                           __nv_bfloat16* __restrict__ yh,
                                           __nv_bfloat16* __restrict__ yl, int i)
{
    float4 v = ((const float4*)x)[i];
    float f[4] = {v.x, v.y, v.z, v.w};
    __nv_bfloat16 h[4], l[4];
#pragma unroll
    for (int j = 0; j < 4; j++) {
        h[j] = __float2bfloat16(f[j]);
        l[j] = __float2bfloat16(f[j] - __bfloat162float(h[j]));
    }
    *(uint2*)(yh + (size_t)4 * i) = make_uint2(pkbf(h[0], h[1]), pkbf(h[2], h[3]));
    *(uint2*)(yl + (size_t)4 * i) = make_uint2(pkbf(l[0], l[1]), pkbf(l[2], l[3]));
}

__global__ void __launch_bounds__(256)
split2_kernel(const float* __restrict__ x, __nv_bfloat16* __restrict__ yh,
              __nv_bfloat16* __restrict__ yl, int n4)
{
    int i  = blockIdx.x * 256 + threadIdx.x;
    int st = gridDim.x * 256;
    if (i < n4)      split_one2(x, yh, yl, i);
    if (i + st < n4) split_one2(x, yh, yl, i + st);
}

// Batched weight split: 3 weight matrices in one launch.
__global__ void __launch_bounds__(256)
split2w_kernel(const float* __restrict__ w0, const float* __restrict__ w1,
               const float* __restrict__ w2, __nv_bfloat16* __restrict__ o0h,
               __nv_bfloat16* __restrict__ o0l, __nv_bfloat16* __restrict__ o1h,
               __nv_bfloat16* __restrict__ o1l, __nv_bfloat16* __restrict__ o2h,
               __nv_bfloat16* __restrict__ o2l, int n4)
{
    int i = blockIdx.x * 256 + threadIdx.x;
    if (i >= 3 * n4) return;
    int which = i / n4;
    int j = i - which * n4;
    const float* src = (which == 0) ? w0 : (which == 1) ? w1 : w2;
    __nv_bfloat16* yh = (which == 0) ? o0h : (which == 1) ? o1h : o2h;
    __nv_bfloat16* yl = (which == 0) ? o0l : (which == 1) ? o1l : o2l;
    split_one2(src, yh, yl, j);
}

// ---------------------------------------------------------------------------
// Softmax over 2048 fp32 logits/row -> dual bf16 planes P_h, P_l.
// ---------------------------------------------------------------------------
__global__ void __launch_bounds__(256)
softmax_split(const float* __restrict__ S, __nv_bfloat16* __restrict__ Ph,
              __nv_bfloat16* __restrict__ Pl)
{
    const float* src = S + (size_t)blockIdx.x * N2;
    __nv_bfloat16* dsth = Ph + (size_t)blockIdx.x * N2;
    __nv_bfloat16* dstl = Pl + (size_t)blockIdx.x * N2;
    const int tid = threadIdx.x;
    __shared__ float red[8];

    float4 v0 = ((const float4*)src)[tid];
    float4 v1 = ((const float4*)src)[tid + 256];

    float m = fmaxf(fmaxf(fmaxf(v0.x, v0.y), fmaxf(v0.z, v0.w)),
                    fmaxf(fmaxf(v1.x, v1.y), fmaxf(v1.z, v1.w)));
#pragma unroll
    for (int o = 16; o > 0; o >>= 1) m = fmaxf(m, __shfl_xor_sync(~0u, m, o));
    if ((tid & 31) == 0) red[tid >> 5] = m;
    __syncthreads();
    if (tid < 32) {
        float t = (tid < 8) ? red[tid] : -INFINITY;
#pragma unroll
        for (int o = 4; o > 0; o >>= 1) t = fmaxf(t, __shfl_xor_sync(~0u, t, o));
        if (tid == 0) red[0] = t;
    }
    __syncthreads();
    const float rowMax = red[0];
    __syncthreads();

    v0.x = expf(v0.x - rowMax); v0.y = expf(v0.y - rowMax);
    v0.z = expf(v0.z - rowMax); v0.w = expf(v0.w - rowMax);
    v1.x = expf(v1.x - rowMax); v1.y = expf(v1.y - rowMax);
    v1.z = expf(v1.z - rowMax); v1.w = expf(v1.w - rowMax);

    float s = v0.x + v0.y + v0.z + v0.w + v1.x + v1.y + v1.z + v1.w;
#pragma unroll
    for (int o = 16; o > 0; o >>= 1) s += __shfl_xor_sync(~0u, s, o);
    if ((tid & 31) == 0) red[tid >> 5] = s;
    __syncthreads();
    if (tid < 32) {
        float t = (tid < 8) ? red[tid] : 0.f;
#pragma unroll
        for (int o = 4; o > 0; o >>= 1) t += __shfl_xor_sync(~0u, t, o);
        if (tid == 0) red[0] = t;
    }
    __syncthreads();
    const float inv = 1.0f / red[0];

#pragma unroll
    for (int g = 0; g < 2; g++) {
        float4 v = g ? v1 : v0;
        int idx = g ? (tid + 256) : tid;
        float f[4] = {v.x * inv, v.y * inv, v.z * inv, v.w * inv};
        __nv_bfloat16 h[4], l[4];
#pragma unroll
        for (int j = 0; j < 4; j++) {
            h[j] = __float2bfloat16(f[j]);
            l[j] = __float2bfloat16(f[j] - __bfloat162float(h[j]));
        }
        *(uint2*)(dsth + (size_t)4 * idx) = make_uint2(pkbf(h[0], h[1]), pkbf(h[2], h[3]));
        *(uint2*)(dstl + (size_t)4 * idx) = make_uint2(pkbf(l[0], l[1]), pkbf(l[2], l[3]));
    }
}

// ---------------------------------------------------------------------------
// Launch (R12 buffer plan, verified disjoint per step)
// ---------------------------------------------------------------------------
extern "C" void kernel_launch(void* const* d_in, const int* in_sizes, int n_in,
                              void* d_out, int out_size)
{
    const float* mainf = (const float*)d_in[0];
    const float* feat  = (const float*)d_in[1];
    const float* Wq    = (const float*)d_in[2];
    const float* bq    = (const float*)d_in[3];
    const float* Wk    = (const float*)d_in[4];
    const float* bk    = (const float*)d_in[5];
    const float* Wv    = (const float*)d_in[6];
    const float* bv    = (const float*)d_in[7];
    float* out = (float*)d_out;

    unsigned char* arena;
    cudaGetSymbolAddress((void**)&arena, g_arena);

    __nv_bfloat16* Xm_h = (__nv_bfloat16*)(arena + OFF_R1);
    __nv_bfloat16* Xm_l = (__nv_bfloat16*)(arena + OFF_R1 + HALF32);
    __nv_bfloat16* Xf_h = (__nv_bfloat16*)(arena + OFF_R2);
    __nv_bfloat16* Xf_l = (__nv_bfloat16*)(arena + OFF_R2 + HALF32);
    __nv_bfloat16* Q_h  = (__nv_bfloat16*)(arena + OFF_R3);
    __nv_bfloat16* Q_l  = (__nv_bfloat16*)(arena + OFF_R3 + HALF32);
    __nv_bfloat16* K_h  = (__nv_bfloat16*)(arena + OFF_R1);
    __nv_bfloat16* K_l  = (__nv_bfloat16*)(arena + OFF_R1 + HALF32);
    __nv_bfloat16* Vt_h = (__nv_bfloat16*)(arena + OFF_R4);
    __nv_bfloat16* Vt_l = (__nv_bfloat16*)(arena + OFF_R4 + HALF32);
    float*         S    = (float*)(arena + OFF_R5);
    __nv_bfloat16* P_h  = (__nv_bfloat16*)(arena + OFF_R3);
    __nv_bfloat16* P_l  = (__nv_bfloat16*)(arena + OFF_R1);
    __nv_bfloat16* Wq_h = (__nv_bfloat16*)(arena + OFF_R6);
    __nv_bfloat16* Wq_l = (__nv_bfloat16*)(arena + OFF_R6 + WPLANE);
    __nv_bfloat16* Wk_h = (__nv_bfloat16*)(arena + OFF_R6 + 2 * WPLANE);
    __nv_bfloat16* Wk_l = (__nv_bfloat16*)(arena + OFF_R6 + 3 * WPLANE);
    __nv_bfloat16* Wv_h = (__nv_bfloat16*)(arena + OFF_R6 + 4 * WPLANE);
    __nv_bfloat16* Wv_l = (__nv_bfloat16*)(arena + OFF_R6 + 5 * WPLANE);

    cudaFuncSetAttribute(gemm2<0, false>, cudaFuncAttributeMaxDynamicSharedMemorySize, SMEM_DYN);
    cudaFuncSetAttribute(gemm2<1, true>,  cudaFuncAttributeMaxDynamicSharedMemorySize, SMEM_DYN);
    cudaFuncSetAttribute(gemm2<2, true>,  cudaFuncAttributeMaxDynamicSharedMemorySize, SMEM_DYN);

    const int MX = BATCH * N1;   // 16384

    // 1) split-encode inputs (2 launches) and all weights (1 launch)
    {
        int n4i = MX * DIM / 4;       // 4,194,304
        int n4w = DIM * DIM / 4;      // 262,144
        split2_kernel<<<(n4i / 2 + 255) / 256, 256>>>(mainf, Xm_h, Xm_l, n4i);
        split2_kernel<<<(n4i / 2 + 255) / 256, 256>>>(feat,  Xf_h, Xf_l, n4i);
        split2w_kernel<<<(3 * n4w + 255) / 256, 256>>>(Wq, Wk, Wv,
                                                       Wq_h, Wq_l, Wk_h, Wk_l,
                                                       Wv_h, Wv_l, n4w);
    }

    // 2-4) projections: M=16384, N=1024, K=1024
    {
        dim3 g(DIM / BN, MX / BM, 1);
        gemm2<1, true><<<g, 256, SMEM_DYN>>>(Xm_h, Xm_l, Wq_h, Wq_l, bq,
                                             nullptr, Q_h, Q_l, DIM, 0, 0, 0, DIM);
        gemm2<1, true><<<g, 256, SMEM_DYN>>>(Xf_h, Xf_l, Wk_h, Wk_l, bk,
                                             nullptr, K_h, K_l, DIM, 0, 0, 0, DIM);
        gemm2<2, true><<<g, 256, SMEM_DYN>>>(Xf_h, Xf_l, Wv_h, Wv_l, bv,
                                             nullptr, Vt_h, Vt_l, DIM, 0, 0, 0, 0);
    }

    // 5) scores: per-batch M=2048, N=2048, K=1024 -> S fp32
    {
        dim3 g(N2 / BN, N1 / BM, BATCH);
        gemm2<0, false><<<g, 256, SMEM_DYN>>>(Q_h, Q_l, K_h, K_l, nullptr,
                                              S, nullptr, nullptr, DIM,
                                              (size_t)N1 * DIM, (size_t)N2 * DIM,
                                              (size_t)N1 * N2, N2);
    }

    // 6) softmax -> P_h, P_l
    softmax_split<<<BATCH * N1, 256>>>(S, P_h, P_l);

    // 7) out = P @ V : per-batch M=2048, N=1024, K=2048
    {
        dim3 g(DIM / BN, N1 / BM, BATCH);
        gemm2<0, false><<<g, 256, SMEM_DYN>>>(P_h, P_l, Vt_h, Vt_l, nullptr,
                                              out, nullptr, nullptr, N2,
                                              (size_t)N1 * N2, (size_t)DIM * N2,
                                              (size_t)N1 * DIM, DIM);
    }
}

// round 15
// speedup vs baseline: 1.0242x; 1.0021x over previous
#include <cuda_runtime.h>
#include <cuda_bf16.h>
#include <math.h>
#include <stdint.h>

// Problem dims (fixed)
#define BATCH 8
#define N1    2048
#define N2    2048
#define DIM   1024

// ---------------------------------------------------------------------------
// Scratch arena, dual-plane (h|l) operand encoding, K' de-aliased so the
// fused projection launch has no cross-z hazards.
//   R1 @ 0         (64MB): Xm_h|Xm_l
//   R2 @ 67108864  (64MB): Xf_h|Xf_l
//   R3 @ 134217728 (64MB): Q_h|Q_l   -> P_h (Q dead after scores)
//   R7 @ 201326592 (64MB): K_h|K_l   -> P_l (K dead after scores)
//   R4 @ 268435456 (64MB): Vt_h|Vt_l
//   R5 @ 335544320 (128MB): S (fp32)
//   R6 @ 469762048 (12MB): Wq_h,Wq_l,Wk_h,Wk_l,Wv_h,Wv_l
// Step check: fused proj z0 reads R1,R6 writes R3 | z1 reads R2,R6 writes R7 |
// z2 reads R2,R6 writes R4  (all write targets disjoint from all read sources).
// scores reads R3,R7 writes R5. softmax reads R5 writes R3,R7. PV reads
// R3,R7,R4 writes d_out.  All disjoint per step.
// ---------------------------------------------------------------------------
#define HALF32  ((size_t)33554432)
#define OFF_R1  ((size_t)0)
#define OFF_R2  ((size_t)67108864)
#define OFF_R3  ((size_t)134217728)
#define OFF_R7  ((size_t)201326592)
#define OFF_R4  ((size_t)268435456)
#define OFF_R5  ((size_t)335544320)
#define OFF_R6  ((size_t)469762048)
#define WPLANE  ((size_t)2097152)
#define ARENA_BYTES ((size_t)482344960)

__device__ __align__(1024) unsigned char g_arena[ARENA_BYTES];

// ---------------------------------------------------------------------------
// PTX helpers (legacy mma.sync path; tcgen05 unavailable on this harness)
// ---------------------------------------------------------------------------
__device__ __forceinline__ uint32_t smem_u32(const void* p) {
    return (uint32_t)__cvta_generic_to_shared(p);
}
__device__ __forceinline__ void cp_async16(uint32_t dst, const void* src) {
    asm volatile("cp.async.cg.shared.global [%0], [%1], 16;\n" :: "r"(dst), "l"(src));
}
__device__ __forceinline__ void cp_commit() {
    asm volatile("cp.async.commit_group;\n");
}
__device__ __forceinline__ void cp_wait1() {
    asm volatile("cp.async.wait_group 1;\n");
}
__device__ __forceinline__ void ldsm4(uint32_t& r0, uint32_t& r1, uint32_t& r2, uint32_t& r3,
                                      uint32_t addr) {
    asm volatile("ldmatrix.sync.aligned.m8n8.x4.shared.b16 {%0,%1,%2,%3}, [%4];\n"
                 : "=r"(r0), "=r"(r1), "=r"(r2), "=r"(r3) : "r"(addr));
}
__device__ __forceinline__ void mma16816(float* d, const uint32_t* a, uint32_t b0, uint32_t b1) {
    asm volatile("mma.sync.aligned.m16n8k16.row.col.f32.bf16.bf16.f32 "
                 "{%0,%1,%2,%3}, {%4,%5,%6,%7}, {%8,%9}, {%0,%1,%2,%3};\n"
                 : "+f"(d[0]), "+f"(d[1]), "+f"(d[2]), "+f"(d[3])
                 : "r"(a[0]), "r"(a[1]), "r"(a[2]), "r"(a[3]), "r"(b0), "r"(b1));
}
__device__ __forceinline__ uint32_t pkbf(__nv_bfloat16 a, __nv_bfloat16 b) {
    return (uint32_t)__bfloat16_as_ushort(a) | ((uint32_t)__bfloat16_as_ushort(b) << 16);
}

// R4-validated swizzle: logical [128 rows][32 k] bf16 (64B rows), two logical
// rows packed per 128B physical row, 16B chunks XORed -> conflict-free.
__device__ __forceinline__ uint32_t sw_off(int r, int c) {
    int pr = r >> 1;
    int pc = ((r & 1) << 2) | c;
    return (uint32_t)(pr * 128 + ((pc ^ (pr & 7)) << 4));
}

// ---------------------------------------------------------------------------
// Dual-plane NT bf16 GEMM core pieces (R14 mainloop, unchanged):
// C = Ah*Bh^T + Ah*Bl^T + Al*Bh^T, fp32 accum.  CTA 128x128, BK=32,
// 256 threads (2x4 warps, 64x32/warp), 3-stage cp.async ring, one sync/iter,
// 2 CTAs/SM.  Per warp-stage: 24 ldsm then 96 MMA.
// ---------------------------------------------------------------------------
#define BM 128
#define BN 128
#define BK 32
#define STAGES 3
#define STG_BYTES 32768u          // Ah 8K | Al 8K | Bh 8K | Bl 8K
#define SMEM_DYN  (STAGES * STG_BYTES)

__device__ __forceinline__ void load_stage2(const __nv_bfloat16* Ah, const __nv_bfloat16* Al,
                                            const __nv_bfloat16* Bh, const __nv_bfloat16* Bl,
                                            int K, int mBase, int nBase,
                                            uint32_t sbase, int s, int k0, int tid)
{
    const uint32_t st = sbase + (uint32_t)s * STG_BYTES;
#pragma unroll
    for (int p = 0; p < 2; p++) {
        int id = tid + p * 256;       // 0..511
        int r  = id >> 2;             // 0..127
        int c  = id & 3;              // 0..3
        uint32_t u = sw_off(r, c);
        const size_t ao = (size_t)(mBase + r) * K + k0 + c * 8;
        const size_t bo = (size_t)(nBase + r) * K + k0 + c * 8;
        cp_async16(st + u,           Ah + ao);
        cp_async16(st + 8192u + u,   Al + ao);
        cp_async16(st + 16384u + u,  Bh + bo);
        cp_async16(st + 24576u + u,  Bl + bo);
    }
    cp_commit();
}

__device__ __forceinline__ void fetch_a(uint32_t base, int wm, int lane, int ks,
                                        uint32_t a[4][4])
{
    const int lrow = lane & 15;
    const int lkc  = lane >> 4;
#pragma unroll
    for (int mi = 0; mi < 4; mi++) {
        int r = wm * 64 + mi * 16 + lrow;
        ldsm4(a[mi][0], a[mi][1], a[mi][2], a[mi][3], base + sw_off(r, ks * 2 + lkc));
    }
}
__device__ __forceinline__ void fetch_b(uint32_t base, int wn, int lane, int ks,
                                        uint32_t b[2][4])
{
    const int lrow = lane & 15;
    const int lkc  = lane >> 4;
#pragma unroll
    for (int bi = 0; bi < 2; bi++) {
        int r = wn * 32 + bi * 16 + lrow;
        ldsm4(b[bi][0], b[bi][1], b[bi][2], b[bi][3], base + sw_off(r, ks * 2 + lkc));
    }
}
__device__ __forceinline__ void mma_frags(const uint32_t a[4][4], const uint32_t b[2][4],
                                          float acc[4][4][4])
{
#pragma unroll
    for (int mi = 0; mi < 4; mi++)
#pragma unroll
        for (int ni = 0; ni < 4; ni++)
            mma16816(acc[mi][ni], a[mi], b[ni >> 1][ni & 1], b[ni >> 1][2 + (ni & 1)]);
}

// shared mainloop body
__device__ __forceinline__ void gemm_mainloop(const __nv_bfloat16* Ah, const __nv_bfloat16* Al,
                                              const __nv_bfloat16* Bh, const __nv_bfloat16* Bl,
                                              int K, int mBase, int nBase, uint32_t sbase,
                                              int tid, int wm, int wn, int lane,
                                              float acc[4][4][4])
{
    const int KT = K / BK;
    load_stage2(Ah, Al, Bh, Bl, K, mBase, nBase, sbase, 0, 0,  tid);
    load_stage2(Ah, Al, Bh, Bl, K, mBase, nBase, sbase, 1, BK, tid);

    for (int kt = 0; kt < KT; kt++) {
        const int s = kt % STAGES;
        const uint32_t st = sbase + (uint32_t)s * STG_BYTES;
        cp_wait1();
        __syncthreads();
        if (kt + 2 < KT)
            load_stage2(Ah, Al, Bh, Bl, K, mBase, nBase, sbase,
                        (kt + 2) % STAGES, (kt + 2) * BK, tid);
        else
            cp_commit();

#pragma unroll
        for (int ks = 0; ks < 2; ks++) {
            uint32_t a_h[4][4], a_l[4][4], b_h[2][4], b_l[2][4];
            fetch_a(st,           wm, lane, ks, a_h);
            fetch_b(st + 16384u,  wn, lane, ks, b_h);
            fetch_a(st + 8192u,   wm, lane, ks, a_l);
            fetch_b(st + 24576u,  wn, lane, ks, b_l);
            mma_frags(a_h, b_h, acc);
            mma_frags(a_l, b_h, acc);
            mma_frags(a_h, b_l, acc);
        }
    }
}

// ---------------------------------------------------------------------------
// Fused projection kernel: blockIdx.z selects Q (z=0), K (z=1), V (z=2).
// One launch, 3072 CTAs -> 10.4 waves (vs 3 x 3.46-wave launches).
// ---------------------------------------------------------------------------
__global__ void __launch_bounds__(256, 2)
proj3_gemm(const __nv_bfloat16* __restrict__ Xm_h, const __nv_bfloat16* __restrict__ Xm_l,
           const __nv_bfloat16* __restrict__ Xf_h, const __nv_bfloat16* __restrict__ Xf_l,
           const __nv_bfloat16* __restrict__ Wq_h, const __nv_bfloat16* __restrict__ Wq_l,
           const __nv_bfloat16* __restrict__ Wk_h, const __nv_bfloat16* __restrict__ Wk_l,
           const __nv_bfloat16* __restrict__ Wv_h, const __nv_bfloat16* __restrict__ Wv_l,
           const float* __restrict__ bq, const float* __restrict__ bk,
           const float* __restrict__ bv,
           __nv_bfloat16* __restrict__ Q_h, __nv_bfloat16* __restrict__ Q_l,
           __nv_bfloat16* __restrict__ K_h, __nv_bfloat16* __restrict__ K_l,
           __nv_bfloat16* __restrict__ Vt_h, __nv_bfloat16* __restrict__ Vt_l)
{
    extern __shared__ __align__(1024) unsigned char dsm[];
    const uint32_t sbase = smem_u32(dsm);

    const int z = blockIdx.z;
    const __nv_bfloat16 *Ah, *Al, *Bh, *Bl;
    const float* bias;
    __nv_bfloat16 *Ch, *Cl;
    if (z == 0)      { Ah = Xm_h; Al = Xm_l; Bh = Wq_h; Bl = Wq_l; bias = bq; Ch = Q_h;  Cl = Q_l;  }
    else if (z == 1) { Ah = Xf_h; Al = Xf_l; Bh = Wk_h; Bl = Wk_l; bias = bk; Ch = K_h;  Cl = K_l;  }
    else             { Ah = Xf_h; Al = Xf_l; Bh = Wv_h; Bl = Wv_l; bias = bv; Ch = Vt_h; Cl = Vt_l; }

    const int tid  = threadIdx.x;
    const int wid  = tid >> 5, lane = tid & 31;
    const int wm   = wid >> 2, wn = wid & 3;
    const int mBase = blockIdx.y * BM;
    const int nBase = blockIdx.x * BN;

    float acc[4][4][4];
#pragma unroll
    for (int i = 0; i < 4; i++)
#pragma unroll
        for (int j = 0; j < 4; j++)
#pragma unroll
            for (int r = 0; r < 4; r++) acc[i][j][r] = 0.f;

    gemm_mainloop(Ah, Al, Bh, Bl, DIM, mBase, nBase, sbase, tid, wm, wn, lane, acc);

    const int grp = lane >> 2, qid = lane & 3;

    if (z < 2) {               // Q / K: dual h/l planes, row-major ld=DIM
#pragma unroll
        for (int mi = 0; mi < 4; mi++)
#pragma unroll
            for (int ni = 0; ni < 4; ni++) {
                int m0 = mBase + wm * 64 + mi * 16 + grp;
                int n0 = nBase + wn * 32 + ni * 8 + qid * 2;
                float bv0 = bias[n0];
                float bv1 = bias[n0 + 1];
#pragma unroll
                for (int rr = 0; rr < 2; rr++) {
                    int m = m0 + rr * 8;
                    float c0 = acc[mi][ni][rr * 2 + 0] + bv0;
                    float c1 = acc[mi][ni][rr * 2 + 1] + bv1;
                    __nv_bfloat16 h0 = __float2bfloat16(c0);
                    __nv_bfloat16 l0 = __float2bfloat16(c0 - __bfloat162float(h0));
                    __nv_bfloat16 h1 = __float2bfloat16(c1);
                    __nv_bfloat16 l1 = __float2bfloat16(c1 - __bfloat162float(h1));
                    *(uint32_t*)(Ch + (size_t)m * DIM + n0) = pkbf(h0, h1);
                    *(uint32_t*)(Cl + (size_t)m * DIM + n0) = pkbf(l0, l1);
                }
            }
    } else {                   // V: scatter C[m][n] -> Vt[b][n][m%N2]
#pragma unroll
        for (int mi = 0; mi < 4; mi++)
#pragma unroll
            for (int ni = 0; ni < 4; ni++) {
                int m0 = mBase + wm * 64 + mi * 16 + grp;
                int n0 = nBase + wn * 32 + ni * 8 + qid * 2;
#pragma unroll
                for (int rr = 0; rr < 2; rr++) {
                    int m  = m0 + rr * 8;
                    int b  = m >> 11;
                    int mm = m & 2047;
#pragma unroll
                    for (int cc = 0; cc < 2; cc++) {
                        int n   = n0 + cc;
                        float c = acc[mi][ni][rr * 2 + cc] + bias[n];
                        __nv_bfloat16 h = __float2bfloat16(c);
                        __nv_bfloat16 l = __float2bfloat16(c - __bfloat162float(h));
                        size_t off = (size_t)b * ((size_t)DIM * N2) + (size_t)n * N2 + mm;
                        Ch[off] = h;
                        Cl[off] = l;
                    }
                }
            }
    }
}

// ---------------------------------------------------------------------------
// fp32-output GEMM (scores and PV), R14-identical.
// ---------------------------------------------------------------------------
__global__ void __launch_bounds__(256, 2)
gemm2f(const __nv_bfloat16* __restrict__ Ah, const __nv_bfloat16* __restrict__ Al,
       const __nv_bfloat16* __restrict__ Bh, const __nv_bfloat16* __restrict__ Bl,
       float* __restrict__ Cf, int K, size_t strA, size_t strB, size_t strC, int ldc)
{
    extern __shared__ __align__(1024) unsigned char dsm[];
    const uint32_t sbase = smem_u32(dsm);

    Ah += (size_t)blockIdx.z * strA;
    Al += (size_t)blockIdx.z * strA;
    Bh += (size_t)blockIdx.z * strB;
    Bl += (size_t)blockIdx.z * strB;

    const int tid  = threadIdx.x;
    const int wid  = tid >> 5, lane = tid & 31;
    const int wm   = wid >> 2, wn = wid & 3;
    const int mBase = blockIdx.y * BM;
    const int nBase = blockIdx.x * BN;

    float acc[4][4][4];
#pragma unroll
    for (int i = 0; i < 4; i++)
#pragma unroll
        for (int j = 0; j < 4; j++)
#pragma unroll
            for (int r = 0; r < 4; r++) acc[i][j][r] = 0.f;

    gemm_mainloop(Ah, Al, Bh, Bl, K, mBase, nBase, sbase, tid, wm, wn, lane, acc);

    const int grp = lane >> 2, qid = lane & 3;
    float* C = Cf + (size_t)blockIdx.z * strC;
#pragma unroll
    for (int mi = 0; mi < 4; mi++)
#pragma unroll
        for (int ni = 0; ni < 4; ni++) {
            int m0 = mBase + wm * 64 + mi * 16 + grp;
            int n0 = nBase + wn * 32 + ni * 8 + qid * 2;
            *(float2*)(C + (size_t)m0 * ldc + n0) =
                make_float2(acc[mi][ni][0], acc[mi][ni][1]);
            *(float2*)(C + (size_t)(m0 + 8) * ldc + n0) =
                make_float2(acc[mi][ni][2], acc[mi][ni][3]);
        }
}

// ---------------------------------------------------------------------------
// fp32 -> dual bf16 planes (h, l).  2 independent float4 per thread.
// ---------------------------------------------------------------------------
__device__ __forceinline__ void split_one2(const float* __restrict__ x,
                                           __nv_bfloat16* __restrict__ yh,
                                           __nv_bfloat16* __restrict__ yl, int i)
{
    float4 v = ((const float4*)x)[i];
    float f[4] = {v.x, v.y, v.z, v.w};
    __nv_bfloat16 h[4], l[4];
#pragma unroll
    for (int j = 0; j < 4; j++) {
        h[j] = __float2bfloat16(f[j]);
        l[j] = __float2bfloat16(f[j] - __bfloat162float(h[j]));
    }
    *(uint2*)(yh + (size_t)4 * i) = make_uint2(pkbf(h[0], h[1]), pkbf(h[2], h[3]));
    *(uint2*)(yl + (size_t)4 * i) = make_uint2(pkbf(l[0], l[1]), pkbf(l[2], l[3]));
}

__global__ void __launch_bounds__(256)
split2_kernel(const float* __restrict__ x, __nv_bfloat16* __restrict__ yh,
              __nv_bfloat16* __restrict__ yl, int n4)
{
    int i  = blockIdx.x * 256 + threadIdx.x;
    int st = gridDim.x * 256;
    if (i < n4)      split_one2(x, yh, yl, i);
    if (i + st < n4) split_one2(x, yh, yl, i + st);
}

// Batched weight split: 3 weight matrices in one launch.
__global__ void __launch_bounds__(256)
split2w_kernel(const float* __restrict__ w0, const float* __restrict__ w1,
               const float* __restrict__ w2, __nv_bfloat16* __restrict__ o0h,
               __nv_bfloat16* __restrict__ o0l, __nv_bfloat16* __restrict__ o1h,
               __nv_bfloat16* __restrict__ o1l, __nv_bfloat16* __restrict__ o2h,
               __nv_bfloat16* __restrict__ o2l, int n4)
{
    int i = blockIdx.x * 256 + threadIdx.x;
    if (i >= 3 * n4) return;
    int which = i / n4;
    int j = i - which * n4;
    const float* src = (which == 0) ? w0 : (which == 1) ? w1 : w2;
    __nv_bfloat16* yh = (which == 0) ? o0h : (which == 1) ? o1h : o2h;
    __nv_bfloat16* yl = (which == 0) ? o0l : (which == 1) ? o1l : o2l;
    split_one2(src, yh, yl, j);
}

// ---------------------------------------------------------------------------
// Softmax over 2048 fp32 logits/row -> dual bf16 planes P_h, P_l.
// ---------------------------------------------------------------------------
__global__ void __launch_bounds__(256)
softmax_split(const float* __restrict__ S, __nv_bfloat16* __restrict__ Ph,
              __nv_bfloat16* __restrict__ Pl)
{
    const float* src = S + (size_t)blockIdx.x * N2;
    __nv_bfloat16* dsth = Ph + (size_t)blockIdx.x * N2;
    __nv_bfloat16* dstl = Pl + (size_t)blockIdx.x * N2;
    const int tid = threadIdx.x;
    __shared__ float red[8];

    float4 v0 = ((const float4*)src)[tid];
    float4 v1 = ((const float4*)src)[tid + 256];

    float m = fmaxf(fmaxf(fmaxf(v0.x, v0.y), fmaxf(v0.z, v0.w)),
                    fmaxf(fmaxf(v1.x, v1.y), fmaxf(v1.z, v1.w)));
#pragma unroll
    for (int o = 16; o > 0; o >>= 1) m = fmaxf(m, __shfl_xor_sync(~0u, m, o));
    if ((tid & 31) == 0) red[tid >> 5] = m;
    __syncthreads();
    if (tid < 32) {
        float t = (tid < 8) ? red[tid] : -INFINITY;
#pragma unroll
        for (int o = 4; o > 0; o >>= 1) t = fmaxf(t, __shfl_xor_sync(~0u, t, o));
        if (tid == 0) red[0] = t;
    }
    __syncthreads();
    const float rowMax = red[0];
    __syncthreads();

    v0.x = expf(v0.x - rowMax); v0.y = expf(v0.y - rowMax);
    v0.z = expf(v0.z - rowMax); v0.w = expf(v0.w - rowMax);
    v1.x = expf(v1.x - rowMax); v1.y = expf(v1.y - rowMax);
    v1.z = expf(v1.z - rowMax); v1.w = expf(v1.w - rowMax);

    float s = v0.x + v0.y + v0.z + v0.w + v1.x + v1.y + v1.z + v1.w;
#pragma unroll
    for (int o = 16; o > 0; o >>= 1) s += __shfl_xor_sync(~0u, s, o);
    if ((tid & 31) == 0) red[tid >> 5] = s;
    __syncthreads();
    if (tid < 32) {
        float t = (tid < 8) ? red[tid] : 0.f;
#pragma unroll
        for (int o = 4; o > 0; o >>= 1) t += __shfl_xor_sync(~0u, t, o);
        if (tid == 0) red[0] = t;
    }
    __syncthreads();
    const float inv = 1.0f / red[0];

#pragma unroll
    for (int g = 0; g < 2; g++) {
        float4 v = g ? v1 : v0;
        int idx = g ? (tid + 256) : tid;
        float f[4] = {v.x * inv, v.y * inv, v.z * inv, v.w * inv};
        __nv_bfloat16 h[4], l[4];
#pragma unroll
        for (int j = 0; j < 4; j++) {
            h[j] = __float2bfloat16(f[j]);
            l[j] = __float2bfloat16(f[j] - __bfloat162float(h[j]));
        }
        *(uint2*)(dsth + (size_t)4 * idx) = make_uint2(pkbf(h[0], h[1]), pkbf(h[2], h[3]));
        *(uint2*)(dstl + (size_t)4 * idx) = make_uint2(pkbf(l[0], l[1]), pkbf(l[2], l[3]));
    }
}

// ---------------------------------------------------------------------------
// Launch
// ---------------------------------------------------------------------------
extern "C" void kernel_launch(void* const* d_in, const int* in_sizes, int n_in,
                              void* d_out, int out_size)
{
    const float* mainf = (const float*)d_in[0];
    const float* feat  = (const float*)d_in[1];
    const float* Wq    = (const float*)d_in[2];
    const float* bq    = (const float*)d_in[3];
    const float* Wk    = (const float*)d_in[4];
    const float* bk    = (const float*)d_in[5];
    const float* Wv    = (const float*)d_in[6];
    const float* bv    = (const float*)d_in[7];
    float* out = (float*)d_out;

    unsigned char* arena;
    cudaGetSymbolAddress((void**)&arena, g_arena);

    __nv_bfloat16* Xm_h = (__nv_bfloat16*)(arena + OFF_R1);
    __nv_bfloat16* Xm_l = (__nv_bfloat16*)(arena + OFF_R1 + HALF32);
    __nv_bfloat16* Xf_h = (__nv_bfloat16*)(arena + OFF_R2);
    __nv_bfloat16* Xf_l = (__nv_bfloat16*)(arena + OFF_R2 + HALF32);
    __nv_bfloat16* Q_h  = (__nv_bfloat16*)(arena + OFF_R3);
    __nv_bfloat16* Q_l  = (__nv_bfloat16*)(arena + OFF_R3 + HALF32);
    __nv_bfloat16* K_h  = (__nv_bfloat16*)(arena + OFF_R7);
    __nv_bfloat16* K_l  = (__nv_bfloat16*)(arena + OFF_R7 + HALF32);
    __nv_bfloat16* Vt_h = (__nv_bfloat16*)(arena + OFF_R4);
    __nv_bfloat16* Vt_l = (__nv_bfloat16*)(arena + OFF_R4 + HALF32);
    float*         S    = (float*)(arena + OFF_R5);
    __nv_bfloat16* P_h  = (__nv_bfloat16*)(arena + OFF_R3);   // Q dead
    __nv_bfloat16* P_l  = (__nv_bfloat16*)(arena + OFF_R7);   // K dead
    __nv_bfloat16* Wq_h = (__nv_bfloat16*)(arena + OFF_R6);
    __nv_bfloat16* Wq_l = (__nv_bfloat16*)(arena + OFF_R6 + WPLANE);
    __nv_bfloat16* Wk_h = (__nv_bfloat16*)(arena + OFF_R6 + 2 * WPLANE);
    __nv_bfloat16* Wk_l = (__nv_bfloat16*)(arena + OFF_R6 + 3 * WPLANE);
    __nv_bfloat16* Wv_h = (__nv_bfloat16*)(arena + OFF_R6 + 4 * WPLANE);
    __nv_bfloat16* Wv_l = (__nv_bfloat16*)(arena + OFF_R6 + 5 * WPLANE);

    cudaFuncSetAttribute(proj3_gemm, cudaFuncAttributeMaxDynamicSharedMemorySize, SMEM_DYN);
    cudaFuncSetAttribute(gemm2f,     cudaFuncAttributeMaxDynamicSharedMemorySize, SMEM_DYN);

    const int MX = BATCH * N1;   // 16384

    // 1) split-encode inputs (2 launches) and all weights (1 launch)
    {
        int n4i = MX * DIM / 4;
        int n4w = DIM * DIM / 4;
        split2_kernel<<<(n4i / 2 + 255) / 256, 256>>>(mainf, Xm_h, Xm_l, n4i);
        split2_kernel<<<(n4i / 2 + 255) / 256, 256>>>(feat,  Xf_h, Xf_l, n4i);
        split2w_kernel<<<(3 * n4w + 255) / 256, 256>>>(Wq, Wk, Wv,
                                                       Wq_h, Wq_l, Wk_h, Wk_l,
                                                       Wv_h, Wv_l, n4w);
    }

    // 2) fused Q/K/V projections: one launch, grid (8, 128, 3) = 3072 CTAs
    {
        dim3 g(DIM / BN, MX / BM, 3);
        proj3_gemm<<<g, 256, SMEM_DYN>>>(Xm_h, Xm_l, Xf_h, Xf_l,
                                         Wq_h, Wq_l, Wk_h, Wk_l, Wv_h, Wv_l,
                                         bq, bk, bv,
                                         Q_h, Q_l, K_h, K_l, Vt_h, Vt_l);
    }

    // 3) scores: per-batch M=2048, N=2048, K=1024 -> S fp32
    {
        dim3 g(N2 / BN, N1 / BM, BATCH);
        gemm2f<<<g, 256, SMEM_DYN>>>(Q_h, Q_l, K_h, K_l, S, DIM,
                                     (size_t)N1 * DIM, (size_t)N2 * DIM,
                                     (size_t)N1 * N2, N2);
    }

    // 4) softmax -> P_h, P_l
    softmax_split<<<BATCH * N1, 256>>>(S, P_h, P_l);

    // 5) out = P @ V : per-batch M=2048, N=1024, K=2048
    {
        dim3 g(DIM / BN, N1 / BM, BATCH);
        gemm2f<<<g, 256, SMEM_DYN>>>(P_h, P_l, Vt_h, Vt_l, out, N2,
                                     (size_t)N1 * N2, (size_t)DIM * N2,
                                     (size_t)N1 * DIM, DIM);
    }
}